// round 4
// baseline (speedup 1.0000x reference)
#include <cuda_runtime.h>

// DenseTNT postprocess: per-batch greedy NMS over 4096 goal candidates.
// Exact sorted-scan-equivalent NMS via rounds of block-wide top-2-by-key
// argmax. Key = (ordered_float(score) << 32) | (~idx)  (stable-sort tiebreak).
// Per round: accept top-1; accept top-2 too iff >=2m from top-1 (exact:
// top-2 is the next-highest unsuppressed candidate; if rejected it is
// suppressed by top-1's kill pass anyway).

#define B_       128
#define N_       4096
#define MODES_   6
#define THRESH2_ 4.0f
#define TPB_     512
#define PER_     8           // candidates per thread (contiguous chunk)
#define NW_      (TPB_ / 32) // 16 warps

typedef unsigned long long u64;
struct __align__(16) Part2 { u64 k1, k2; };

__device__ __forceinline__ u64 umax64(u64 a, u64 b) { return a > b ? a : b; }
__device__ __forceinline__ u64 umin64(u64 a, u64 b) { return a < b ? a : b; }

__global__ __launch_bounds__(TPB_, 1)
void densetnt_nms_kernel(const float* __restrict__ scores,   // [B, N]
                         const float* __restrict__ trajs,    // [B, 60, N]
                         const float* __restrict__ goals,    // [B, 2, N]
                         float* __restrict__ out)            // [B,6,30,2] ++ [B,6]
{
    const int b    = blockIdx.x;
    const int t    = threadIdx.x;
    const int w    = t >> 5;
    const int lane = t & 31;

    __shared__ float2 sgoal[N_];          // 32 KB goal mirror (broadcast reads)
    __shared__ Part2  red[2][NW_];        // parity double-buffer
    __shared__ int    sel_s[MODES_];
    __shared__ float  ssc_s[MODES_];

    const float* sc = scores + (size_t)b * N_     + (size_t)t * PER_;
    const float* gx = goals  + (size_t)b * 2 * N_ + (size_t)t * PER_;
    const float* gy = gx + N_;

    // Vectorized load of this thread's contiguous 8-candidate chunk.
    float4 s0 = ((const float4*)sc)[0], s1 = ((const float4*)sc)[1];
    float4 a0 = ((const float4*)gx)[0], a1 = ((const float4*)gx)[1];
    float4 c0 = ((const float4*)gy)[0], c1 = ((const float4*)gy)[1];

    float x[PER_]  = {a0.x, a0.y, a0.z, a0.w, a1.x, a1.y, a1.z, a1.w};
    float y[PER_]  = {c0.x, c0.y, c0.z, c0.w, c1.x, c1.y, c1.z, c1.w};
    float sv[PER_] = {s0.x, s0.y, s0.z, s0.w, s1.x, s1.y, s1.z, s1.w};

    u64 key[PER_];
#pragma unroll
    for (int j = 0; j < PER_; j++) {
        int i = t * PER_ + j;
        sgoal[i] = make_float2(x[j], y[j]);
        unsigned u  = __float_as_uint(sv[j]);
        unsigned os = u ^ (0x80000000u | (unsigned)(((int)u) >> 31)); // order-preserving
        key[j] = ((u64)os << 32) | (u64)(0xFFFFFFFFu - (unsigned)i);
    }
    __syncthreads();   // sgoal ready

    int count = 0;
    for (int r = 0; r < MODES_ && count < MODES_; r++) {
        // --- local top-2 over the 8 (killed -> key 0) ---
        u64 k1 = 0ull, k2 = 0ull;
#pragma unroll
        for (int j = 0; j < PER_; j++) {
            u64 k = key[j];
            u64 n1 = umax64(k1, k);
            k2 = umax64(k2, umin64(k1, k));
            k1 = n1;
        }
        // --- warp top-2 merge (5 shfl levels) ---
#pragma unroll
        for (int o = 16; o > 0; o >>= 1) {
            u64 o1 = __shfl_xor_sync(0xFFFFFFFFu, k1, o);
            u64 o2 = __shfl_xor_sync(0xFFFFFFFFu, k2, o);
            u64 n1 = umax64(k1, o1);
            k2 = umax64(umin64(k1, o1), umax64(k2, o2));
            k1 = n1;
        }
        if (lane == 0) { Part2 p; p.k1 = k1; p.k2 = k2; red[r & 1][w] = p; }
        __syncthreads();   // only barrier this round

        // --- every thread merges the 16 warp partials (broadcast LDS) ---
        u64 w1 = 0ull, w2 = 0ull;
#pragma unroll
        for (int ww = 0; ww < NW_; ww++) {
            Part2 p = red[r & 1][ww];
            u64 n1 = umax64(w1, p.k1);
            w2 = umax64(umin64(w1, p.k1), umax64(w2, p.k2));
            w1 = n1;
        }

        if (w1 == 0ull) break;   // everything suppressed (uniform)

        // --- accept top-1 ---
        const int i1 = (int)(0xFFFFFFFFu - (unsigned)(w1 & 0xFFFFFFFFull));
        const float2 g1 = sgoal[i1];
        if (t == 0) {
            unsigned os = (unsigned)(w1 >> 32);
            sel_s[count] = i1;
            ssc_s[count] = __uint_as_float(os ^ (0x80000000u | (unsigned)(((int)~os) >> 31)));
        }
        count++;

        // --- conditionally accept top-2 (exactness: see header comment) ---
        int   nacc = 1;
        float ax2 = 0.f, ay2 = 0.f;
        if (count < MODES_ && w2 != 0ull) {
            const int i2 = (int)(0xFFFFFFFFu - (unsigned)(w2 & 0xFFFFFFFFull));
            const float2 g2 = sgoal[i2];
            float dx = g2.x - g1.x, dy = g2.y - g1.y;
            if (dx * dx + dy * dy >= THRESH2_) {
                if (t == 0) {
                    unsigned os = (unsigned)(w2 >> 32);
                    sel_s[count] = i2;
                    ssc_s[count] = __uint_as_float(os ^ (0x80000000u | (unsigned)(((int)~os) >> 31)));
                }
                count++;
                nacc = 2; ax2 = g2.x; ay2 = g2.y;
            }
        }

        // --- kill pass vs accepted winners ---
#pragma unroll
        for (int j = 0; j < PER_; j++) {
            float dx1 = x[j] - g1.x, dy1 = y[j] - g1.y;
            bool dead = (dx1 * dx1 + dy1 * dy1 < THRESH2_);
            if (nacc == 2) {
                float dx2 = x[j] - ax2, dy2 = y[j] - ay2;
                dead |= (dx2 * dx2 + dy2 * dy2 < THRESH2_);
            }
            if (dead) key[j] = 0ull;
        }
        // no trailing barrier: next round writes the other parity buffer; its
        // barrier bounds warp skew to one round.
    }

    // fallback: unfilled slots -> first pick (global top-1)
    if (t == 0) {
        for (int m = count; m < MODES_; m++) { sel_s[m] = sel_s[0]; ssc_s[m] = ssc_s[0]; }
    }
    __syncthreads();

    // --- gather: out trajs [B,6,30,2] then scores [B,6] ---
    const float* tb = trajs + (size_t)b * 60 * N_;
    float* ob = out + (size_t)b * MODES_ * 60;
    for (int e = t; e < MODES_ * 60; e += TPB_) {
        int m = e / 60;
        int k = e - m * 60;
        ob[e] = __ldg(tb + (size_t)k * N_ + sel_s[m]);
    }
    if (t < MODES_) {
        out[(size_t)B_ * MODES_ * 60 + (size_t)b * MODES_ + t] = ssc_s[t];
    }
}

extern "C" void kernel_launch(void* const* d_in, const int* in_sizes, int n_in,
                              void* d_out, int out_size)
{
    const float* goals_scores = (const float*)d_in[0];  // [128, 4096]
    const float* traj_preds   = (const float*)d_in[1];  // [128, 60, 4096]
    const float* pred_goals   = (const float*)d_in[2];  // [128, 2, 4096]
    float* out = (float*)d_out;

    densetnt_nms_kernel<<<B_, TPB_>>>(goals_scores, traj_preds, pred_goals, out);
}

// round 5
// speedup vs baseline: 1.4102x; 1.4102x over previous
#include <cuda_runtime.h>

// DenseTNT postprocess: per-batch greedy NMS over 4096 goal candidates.
// k-th pick = argmax score among candidates not suppressed (d2 < 4.0) by
// already-picked goals. Tie-break: equal score -> lower original index,
// encoded in 64-bit key = (ordered_float(score) << 32) | (~idx).
// Structure: 6 fully-unrolled rounds, u64 shfl-max chain, sgoal smem
// broadcast, parity-double-buffered warp partials, ONE barrier per round.

#define B_       128
#define N_       4096
#define MODES_   6
#define THRESH2_ 4.0f
#define TPB_     512
#define PER_     8           // candidates per thread (contiguous chunk)
#define NW_      (TPB_ / 32) // 16 warps

typedef unsigned long long u64;

__global__ __launch_bounds__(TPB_, 1)
void densetnt_nms_kernel(const float* __restrict__ scores,   // [B, N]
                         const float* __restrict__ trajs,    // [B, 60, N]
                         const float* __restrict__ goals,    // [B, 2, N]
                         float* __restrict__ out)            // [B,6,30,2] ++ [B,6]
{
    const int b    = blockIdx.x;
    const int t    = threadIdx.x;
    const int w    = t >> 5;
    const int lane = t & 31;

    __shared__ float2 sgoal[N_];          // 32 KB goal mirror (broadcast reads)
    __shared__ u64    red[2][NW_];        // parity double-buffer
    __shared__ u64    win_s[MODES_];
    __shared__ int    sel_s[MODES_];
    __shared__ float  ssc_s[MODES_];

    const float* sc = scores + (size_t)b * N_     + (size_t)t * PER_;
    const float* gx = goals  + (size_t)b * 2 * N_ + (size_t)t * PER_;
    const float* gy = gx + N_;

    // Vectorized load of this thread's contiguous 8-candidate chunk.
    float4 s0 = ((const float4*)sc)[0], s1 = ((const float4*)sc)[1];
    float4 a0 = ((const float4*)gx)[0], a1 = ((const float4*)gx)[1];
    float4 c0 = ((const float4*)gy)[0], c1 = ((const float4*)gy)[1];

    float x[PER_]  = {a0.x, a0.y, a0.z, a0.w, a1.x, a1.y, a1.z, a1.w};
    float y[PER_]  = {c0.x, c0.y, c0.z, c0.w, c1.x, c1.y, c1.z, c1.w};
    float sv[PER_] = {s0.x, s0.y, s0.z, s0.w, s1.x, s1.y, s1.z, s1.w};

    // Fill the goal mirror with 4 STS.128 (interleave x/y pairs).
    {
        float4* dst = (float4*)(sgoal + (size_t)t * PER_);
        dst[0] = make_float4(x[0], y[0], x[1], y[1]);
        dst[1] = make_float4(x[2], y[2], x[3], y[3]);
        dst[2] = make_float4(x[4], y[4], x[5], y[5]);
        dst[3] = make_float4(x[6], y[6], x[7], y[7]);
    }

    u64 key[PER_];
#pragma unroll
    for (int j = 0; j < PER_; j++) {
        unsigned i  = (unsigned)(t * PER_ + j);
        unsigned u  = __float_as_uint(sv[j]);
        unsigned os = u ^ (0x80000000u | (unsigned)(((int)u) >> 31)); // order-preserving
        key[j] = ((u64)os << 32) | (u64)(0xFFFFFFFFu - i);
    }
    __syncthreads();   // sgoal ready

#pragma unroll
    for (int m = 0; m < MODES_; m++) {
        // --- local argmax over the 8 (killed -> key==0) ---
        u64 best = key[0];
#pragma unroll
        for (int j = 1; j < PER_; j++) best = key[j] > best ? key[j] : best;

        // --- warp max (5 shfl levels) ---
#pragma unroll
        for (int o = 16; o > 0; o >>= 1) {
            u64 v = __shfl_xor_sync(0xFFFFFFFFu, best, o);
            best = v > best ? v : best;
        }
        if (lane == 0) red[m & 1][w] = best;
        __syncthreads();   // ONLY barrier this round

        // --- every thread merges the 16 warp partials (8x LDS.128) ---
        const ulonglong2* rp = (const ulonglong2*)red[m & 1];
        u64 win = 0ull;
#pragma unroll
        for (int q = 0; q < NW_ / 2; q++) {
            ulonglong2 p = rp[q];
            u64 hi = p.x > p.y ? p.x : p.y;
            win = hi > win ? hi : win;
        }
        if (t == 0) win_s[m] = win;

        if (win != 0ull) {
            const int widx = (int)(0xFFFFFFFFu - (unsigned)(win & 0xFFFFFFFFull));
            const float2 g = sgoal[widx];      // broadcast read
#pragma unroll
            for (int j = 0; j < PER_; j++) {
                float dx = x[j] - g.x;
                float dy = y[j] - g.y;
                if (dx * dx + dy * dy < THRESH2_) key[j] = 0ull;
            }
        }
        // no trailing barrier: next round writes the other parity buffer; the
        // round-(m+1) barrier bounds warp skew to one round.
    }
    __syncthreads();   // win_s[] complete

    // decode selections (empty slot -> round-0 winner = global top-1)
    if (t < MODES_) {
        u64 wv = win_s[t];
        if (wv == 0ull) wv = win_s[0];
        sel_s[t] = (int)(0xFFFFFFFFu - (unsigned)(wv & 0xFFFFFFFFull));
        unsigned os = (unsigned)(wv >> 32);
        ssc_s[t] = __uint_as_float(os ^ (0x80000000u | (unsigned)(((int)~os) >> 31)));
    }
    __syncthreads();

    // gather: out trajs [B,6,30,2] then scores [B,6]
    const float* tb = trajs + (size_t)b * 60 * N_;
    float* ob = out + (size_t)b * MODES_ * 60;
    for (int e = t; e < MODES_ * 60; e += TPB_) {
        int m = e / 60;
        int k = e - m * 60;
        ob[e] = __ldg(tb + (size_t)k * N_ + sel_s[m]);
    }
    if (t < MODES_) {
        out[(size_t)B_ * MODES_ * 60 + (size_t)b * MODES_ + t] = ssc_s[t];
    }
}

extern "C" void kernel_launch(void* const* d_in, const int* in_sizes, int n_in,
                              void* d_out, int out_size)
{
    const float* goals_scores = (const float*)d_in[0];  // [128, 4096]
    const float* traj_preds   = (const float*)d_in[1];  // [128, 60, 4096]
    const float* pred_goals   = (const float*)d_in[2];  // [128, 2, 4096]
    float* out = (float*)d_out;

    densetnt_nms_kernel<<<B_, TPB_>>>(goals_scores, traj_preds, pred_goals, out);
}

// round 6
// speedup vs baseline: 1.4537x; 1.0309x over previous
#include <cuda_runtime.h>

// DenseTNT postprocess: per-batch greedy NMS over 4096 goal candidates.
// k-th pick = argmax score among candidates not suppressed (d2 < 4.0) by
// already-picked goals. Key = (ordered_float(score) << 32) | (~idx) encodes
// stable-sort tie-break (equal score -> lower index).
//
// Lazy suppression: each thread contributes only its current local-best
// candidate to the block argmax. Invariant: entering round m, bk is the
// thread's max key among candidates not suppressed by picks 0..m-1.
// Common path per round: ONE distance check (best vs newest pick).
// Recompute (best won / best suppressed) validates the new best against the
// full pick history; stale candidates are validated before becoming best.

#define B_       128
#define N_       4096
#define MODES_   6
#define THRESH2_ 4.0f
#define TPB_     512
#define PER_     8           // candidates per thread (contiguous chunk)
#define NW_      (TPB_ / 32) // 16 warps

typedef unsigned long long u64;

__global__ __launch_bounds__(TPB_, 1)
void densetnt_nms_kernel(const float* __restrict__ scores,   // [B, N]
                         const float* __restrict__ trajs,    // [B, 60, N]
                         const float* __restrict__ goals,    // [B, 2, N]
                         float* __restrict__ out)            // [B,6,30,2] ++ [B,6]
{
    const int b    = blockIdx.x;
    const int t    = threadIdx.x;
    const int w    = t >> 5;
    const int lane = t & 31;

    __shared__ float2 sgoal[N_];          // 32 KB goal mirror (broadcast reads)
    __shared__ u64    red[2][NW_];        // parity double-buffer
    __shared__ u64    win_s[MODES_];
    __shared__ int    sel_s[MODES_];
    __shared__ float  ssc_s[MODES_];

    const float* sc = scores + (size_t)b * N_     + (size_t)t * PER_;
    const float* gx = goals  + (size_t)b * 2 * N_ + (size_t)t * PER_;
    const float* gy = gx + N_;
    const float* tb = trajs + (size_t)b * 60 * N_;
    float* ob = out + (size_t)b * MODES_ * 60;

    // Vectorized load of this thread's contiguous 8-candidate chunk.
    float4 s0 = ((const float4*)sc)[0], s1 = ((const float4*)sc)[1];
    float4 a0 = ((const float4*)gx)[0], a1 = ((const float4*)gx)[1];
    float4 c0 = ((const float4*)gy)[0], c1 = ((const float4*)gy)[1];

    float x[PER_]  = {a0.x, a0.y, a0.z, a0.w, a1.x, a1.y, a1.z, a1.w};
    float y[PER_]  = {c0.x, c0.y, c0.z, c0.w, c1.x, c1.y, c1.z, c1.w};
    float sv[PER_] = {s0.x, s0.y, s0.z, s0.w, s1.x, s1.y, s1.z, s1.w};

    // Fill goal mirror with 4 STS.128.
    {
        float4* dst = (float4*)(sgoal + (size_t)t * PER_);
        dst[0] = make_float4(x[0], y[0], x[1], y[1]);
        dst[1] = make_float4(x[2], y[2], x[3], y[3]);
        dst[2] = make_float4(x[4], y[4], x[5], y[5]);
        dst[3] = make_float4(x[6], y[6], x[7], y[7]);
    }

    u64 key[PER_];
#pragma unroll
    for (int j = 0; j < PER_; j++) {
        unsigned i  = (unsigned)(t * PER_ + j);
        unsigned u  = __float_as_uint(sv[j]);
        unsigned os = u ^ (0x80000000u | (unsigned)(((int)u) >> 31)); // order-preserving
        key[j] = ((u64)os << 32) | (u64)(0xFFFFFFFFu - i);
    }

    // Initial local best (no picks yet -> no validation needed).
    u64 bk = key[0]; float bx = x[0], by = y[0];
#pragma unroll
    for (int j = 1; j < PER_; j++)
        if (key[j] > bk) { bk = key[j]; bx = x[j]; by = y[j]; }

    float px[MODES_], py[MODES_];   // pick history (static-indexed -> registers)

    __syncthreads();   // sgoal ready

#pragma unroll
    for (int m = 0; m < MODES_; m++) {
        // --- warp max over the 32 lazy local-bests (5 shfl levels) ---
        u64 best = bk;
#pragma unroll
        for (int o = 16; o > 0; o >>= 1) {
            u64 v = __shfl_xor_sync(0xFFFFFFFFu, best, o);
            best = v > best ? v : best;
        }
        if (lane == 0) red[m & 1][w] = best;
        __syncthreads();   // ONLY barrier this round

        // --- all threads merge the 16 warp partials (8x LDS.128) ---
        const ulonglong2* rp = (const ulonglong2*)red[m & 1];
        u64 win = 0ull;
#pragma unroll
        for (int q = 0; q < NW_ / 2; q++) {
            ulonglong2 p = rp[q];
            u64 hi = p.x > p.y ? p.x : p.y;
            win = hi > win ? hi : win;
        }
        if (t == 0) win_s[m] = win;

        if (win != 0ull) {
            const int widx = (int)(0xFFFFFFFFu - (unsigned)(win & 0xFFFFFFFFull));
            const float2 g = sgoal[widx];      // broadcast read
            px[m] = g.x; py[m] = g.y;

            // --- overlapped gather: warps 14-15 fetch mode m's trajectory ---
            if (t >= TPB_ - 64) {
                int e = t - (TPB_ - 64);
                if (e < 60) ob[m * 60 + e] = __ldg(tb + (size_t)e * N_ + widx);
            }

            // --- lazy update of local best ---
            float dx = bx - g.x, dy = by - g.y;
            bool need = (bk == win) | (bk != 0ull && dx * dx + dy * dy < THRESH2_);
            if (need) {
                // remove current best (value match keeps arrays in registers)
#pragma unroll
                for (int j = 0; j < PER_; j++) key[j] = (key[j] == bk) ? 0ull : key[j];
                // recompute + validate against full pick history (rare path)
                for (;;) {
                    u64 nk = key[0]; float nx = x[0], ny = y[0];
#pragma unroll
                    for (int j = 1; j < PER_; j++)
                        if (key[j] > nk) { nk = key[j]; nx = x[j]; ny = y[j]; }
                    if (nk == 0ull) { bk = 0ull; break; }
                    bool sup = false;
#pragma unroll
                    for (int r = 0; r < MODES_; r++) {
                        if (r <= m) {
                            float ddx = nx - px[r], ddy = ny - py[r];
                            sup |= (ddx * ddx + ddy * ddy < THRESH2_);
                        }
                    }
                    if (sup) {
#pragma unroll
                        for (int j = 0; j < PER_; j++) key[j] = (key[j] == nk) ? 0ull : key[j];
                    } else { bk = nk; bx = nx; by = ny; break; }
                }
            }
        }
        // no trailing barrier: next round writes the other parity buffer; the
        // round-(m+1) barrier bounds warp skew to one round.
    }
    __syncthreads();   // win_s[] complete

    // decode selections (empty slot -> round-0 winner = global top-1)
    if (t < MODES_) {
        u64 wv = win_s[t];
        if (wv == 0ull) wv = win_s[0];
        sel_s[t] = (int)(0xFFFFFFFFu - (unsigned)(wv & 0xFFFFFFFFull));
        unsigned os = (unsigned)(wv >> 32);
        ssc_s[t] = __uint_as_float(os ^ (0x80000000u | (unsigned)(((int)~os) >> 31)));
    }
    __syncthreads();

    // tail: only fallback modes (win==0) still need their gather
    for (int e = t; e < MODES_ * 60; e += TPB_) {
        int m = e / 60;
        if (win_s[m] == 0ull) {
            int k = e - m * 60;
            ob[e] = __ldg(tb + (size_t)k * N_ + sel_s[m]);
        }
    }
    if (t < MODES_) {
        out[(size_t)B_ * MODES_ * 60 + (size_t)b * MODES_ + t] = ssc_s[t];
    }
}

extern "C" void kernel_launch(void* const* d_in, const int* in_sizes, int n_in,
                              void* d_out, int out_size)
{
    const float* goals_scores = (const float*)d_in[0];  // [128, 4096]
    const float* traj_preds   = (const float*)d_in[1];  // [128, 60, 4096]
    const float* pred_goals   = (const float*)d_in[2];  // [128, 2, 4096]
    float* out = (float*)d_out;

    densetnt_nms_kernel<<<B_, TPB_>>>(goals_scores, traj_preds, pred_goals, out);
}